// round 2
// baseline (speedup 1.0000x reference)
#include <cuda_runtime.h>

#define RR      512
#define NPIX    (RR*RR)
#define CZ      128
#define CT      64
#define NH      4
#define NT      4
#define TILE    64
#define THREADS 512

// smem layout (float offsets)
#define WQ_OFF   0                      // [128][64]
#define WK_OFF   8192                   // [64] rows, stride 68
#define WV_OFF   (WK_OFF + 64*68)       // [64][64]
#define WO_OFF   (WV_OFF + 4096)        // [64][128]
#define BO_OFF   (WO_OFF + 8192)        // [128]
#define BIAS_OFF (BO_OFF + 128)         // [4]
#define Z_OFF    (BIAS_OFF + 4)         // [64] rows, stride 132
#define Q_OFF    (Z_OFF + 64*132)       // [64] rows, stride 68 (aliased by O)
#define QP_OFF   (Q_OFF + 64*68)        // [64] rows, stride 260 (Qp, then m)
#define SMEM_FLOATS (QP_OFF + 64*260)   // 54404 floats = 217616 B

typedef unsigned long long u64t;

__device__ __forceinline__ u64t pk2(float lo, float hi) {
    u64t r; asm("mov.b64 %0, {%1,%2};" : "=l"(r) : "f"(lo), "f"(hi)); return r;
}
__device__ __forceinline__ void upk2(u64t v, float &a, float &b) {
    asm("mov.b64 {%0,%1}, %2;" : "=f"(a), "=f"(b) : "l"(v));
}
__device__ __forceinline__ void fma2(u64t &acc, u64t a, u64t b) {
    asm("fma.rn.f32x2 %0, %1, %2, %0;" : "+l"(acc) : "l"(a), "l"(b));
}
__device__ __forceinline__ void add2(u64t &acc, u64t b) {
    asm("add.rn.f32x2 %0, %0, %1;" : "+l"(acc) : "l"(b));
}

__global__ void __launch_bounds__(THREADS, 1)
tpa_kernel(const float* __restrict__ t, const float* __restrict__ z,
           const float* __restrict__ mask,
           const float* __restrict__ Wq, const float* __restrict__ Wk,
           const float* __restrict__ Wv, const float* __restrict__ Wo,
           const float* __restrict__ bo, float* __restrict__ out, int ntiles)
{
    extern __shared__ float sm[];
    const int tid = threadIdx.x;

    // one-time weight staging
    for (int i = tid; i < 8192; i += THREADS) sm[WQ_OFF + i] = Wq[i] * 0.25f; // fold 16^-0.5
    for (int i = tid; i < 4096; i += THREADS) {
        int c = i >> 6, j = i & 63;
        sm[WK_OFF + c*68 + j] = Wk[i];
    }
    for (int i = tid; i < 4096; i += THREADS) sm[WV_OFF + i] = Wv[i];
    for (int i = tid; i < 8192; i += THREADS) sm[WO_OFF + i] = Wo[i];
    if (tid < 128) sm[BO_OFF + tid] = bo[tid];
    if (tid < 4)   sm[BIAS_OFF + tid] = 1e5f * (mask[tid] - 1.0f);
    __syncthreads();

    const int p8 = tid >> 3;   // pixel within tile
    const int u  = tid & 7;    // sub-slot

    for (int tile = blockIdx.x; tile < ntiles; tile += gridDim.x) {
        const int n0 = tile * TILE;

        // phase 0: stage Z tile [64][128] (row stride 132)
        {
            const float4* zg = reinterpret_cast<const float4*>(z + (size_t)n0 * CZ);
            #pragma unroll
            for (int r_ = 0; r_ < 4; r_++) {
                int e = tid + r_ * THREADS;          // 0..2047
                float4 v = zg[e];
                *reinterpret_cast<float4*>(&sm[Z_OFF + (e >> 5)*132 + (e & 31)*4]) = v;
            }
        }
        __syncthreads();

        // phase 1: Q = Z @ Wq'   (thread -> pixel p8, cols u*4..+3 and 32+u*4..+3)
        {
            u64t a0 = 0, a1 = 0, a2 = 0, a3 = 0;
            const float* zr  = &sm[Z_OFF + p8*132];
            const float* wq0 = &sm[WQ_OFF + u*4];
            #pragma unroll 2
            for (int c = 0; c < CZ; c += 4) {
                float4 zv = *reinterpret_cast<const float4*>(zr + c);
                #pragma unroll
                for (int k = 0; k < 4; k++) {
                    float zc = (&zv.x)[k];
                    u64t zz = pk2(zc, zc);
                    const float* wr = wq0 + (c + k) * 64;
                    ulonglong2 wa = *reinterpret_cast<const ulonglong2*>(wr);
                    ulonglong2 wb = *reinterpret_cast<const ulonglong2*>(wr + 32);
                    fma2(a0, zz, wa.x); fma2(a1, zz, wa.y);
                    fma2(a2, zz, wb.x); fma2(a3, zz, wb.y);
                }
            }
            float* qo = &sm[Q_OFF + p8*68 + u*4];
            *reinterpret_cast<ulonglong2*>(qo)      = make_ulonglong2(a0, a1);
            *reinterpret_cast<ulonglong2*>(qo + 32) = make_ulonglong2(a2, a3);
        }
        __syncthreads();

        // phase 2: Qp[p][h*64+c] = Q[p][h*16..] . Wk[c][h*16..]
        {
            const int h2  = tid >> 7;
            const int p2  = (tid >> 1) & 63;
            const int par = tid & 1;
            const float* qr = &sm[Q_OFF + p2*68 + h2*16];
            ulonglong2 qA = *reinterpret_cast<const ulonglong2*>(qr);
            ulonglong2 qB = *reinterpret_cast<const ulonglong2*>(qr + 4);
            ulonglong2 qC = *reinterpret_cast<const ulonglong2*>(qr + 8);
            ulonglong2 qD = *reinterpret_cast<const ulonglong2*>(qr + 12);
            float* qpo = &sm[QP_OFF + p2*260 + h2*64];
            const float* wb0 = &sm[WK_OFF + h2*16];
            #pragma unroll 4
            for (int i = 0; i < 32; i++) {
                const int c = 2*i + par;
                const float* wr = wb0 + c*68;
                u64t s0 = 0, s1 = 0;
                ulonglong2 w0 = *reinterpret_cast<const ulonglong2*>(wr);
                ulonglong2 w1 = *reinterpret_cast<const ulonglong2*>(wr + 4);
                ulonglong2 w2 = *reinterpret_cast<const ulonglong2*>(wr + 8);
                ulonglong2 w3 = *reinterpret_cast<const ulonglong2*>(wr + 12);
                fma2(s0, qA.x, w0.x); fma2(s1, qA.y, w0.y);
                fma2(s0, qB.x, w1.x); fma2(s1, qB.y, w1.y);
                fma2(s0, qC.x, w2.x); fma2(s1, qC.y, w2.y);
                fma2(s0, qD.x, w3.x); fma2(s1, qD.y, w3.y);
                float x0, x1, y0, y1; upk2(s0, x0, x1); upk2(s1, y0, y1);
                qpo[c] = (x0 + x1) + (y0 + y1);
            }
        }
        __syncthreads();

        // phase 3: logits + softmax + m   (8 threads per pixel, c-slice u*8..+7)
        {
            const int c0 = u * 8;
            const size_t nglob = (size_t)n0 + p8;
            ulonglong2 tv[NT][2];
            #pragma unroll
            for (int tt = 0; tt < NT; tt++) {
                const float* tp = t + ((size_t)tt * NPIX + nglob) * CT + c0;
                tv[tt][0] = *reinterpret_cast<const ulonglong2*>(tp);
                tv[tt][1] = *reinterpret_cast<const ulonglong2*>(tp + 4);
            }
            float lg[NH][NT];
            const float* qpr = &sm[QP_OFF + p8*260 + c0];
            #pragma unroll
            for (int h = 0; h < NH; h++) {
                ulonglong2 qa = *reinterpret_cast<const ulonglong2*>(qpr + h*64);
                ulonglong2 qb = *reinterpret_cast<const ulonglong2*>(qpr + h*64 + 4);
                #pragma unroll
                for (int tt = 0; tt < NT; tt++) {
                    u64t s = 0;
                    fma2(s, qa.x, tv[tt][0].x);
                    fma2(s, qa.y, tv[tt][0].y);
                    fma2(s, qb.x, tv[tt][1].x);
                    fma2(s, qb.y, tv[tt][1].y);
                    float x0, x1; upk2(s, x0, x1);
                    lg[h][tt] = x0 + x1;
                }
            }
            #pragma unroll
            for (int off = 4; off >= 1; off >>= 1)
                #pragma unroll
                for (int h = 0; h < NH; h++)
                    #pragma unroll
                    for (int tt = 0; tt < NT; tt++)
                        lg[h][tt] += __shfl_xor_sync(0xffffffffu, lg[h][tt], off, 8);

            const float b0 = sm[BIAS_OFF+0], b1 = sm[BIAS_OFF+1];
            const float b2 = sm[BIAS_OFF+2], b3 = sm[BIAS_OFF+3];
            float aw[NH][NT];
            #pragma unroll
            for (int h = 0; h < NH; h++) {
                float l0 = lg[h][0]+b0, l1 = lg[h][1]+b1;
                float l2 = lg[h][2]+b2, l3 = lg[h][3]+b3;
                float mx = fmaxf(fmaxf(l0,l1), fmaxf(l2,l3));
                float e0 = __expf(l0-mx), e1 = __expf(l1-mx);
                float e2 = __expf(l2-mx), e3 = __expf(l3-mx);
                float inv = 1.0f / (e0+e1+e2+e3);
                aw[h][0]=e0*inv; aw[h][1]=e1*inv; aw[h][2]=e2*inv; aw[h][3]=e3*inv;
            }
            __syncwarp();
            float* mp = &sm[QP_OFF + p8*260 + c0];
            #pragma unroll
            for (int h = 0; h < NH; h++) {
                u64t m0 = 0, m1 = 0, m2 = 0, m3 = 0;
                #pragma unroll
                for (int tt = 0; tt < NT; tt++) {
                    u64t av = pk2(aw[h][tt], aw[h][tt]);
                    fma2(m0, av, tv[tt][0].x);
                    fma2(m1, av, tv[tt][0].y);
                    fma2(m2, av, tv[tt][1].x);
                    fma2(m3, av, tv[tt][1].y);
                }
                *reinterpret_cast<ulonglong2*>(mp + h*64)     = make_ulonglong2(m0, m1);
                *reinterpret_cast<ulonglong2*>(mp + h*64 + 4) = make_ulonglong2(m2, m3);
            }
        }
        __syncwarp();

        // phase 4: O[p][hd] = sum_c m[p][hd>>4][c] * Wv[c][hd]  (O aliases Q)
        {
            const float* mA = &sm[QP_OFF + p8*260 + (u >> 2) * 64];  // head u>>2
            const float* mB = mA + 128;                               // head 2+(u>>2)
            u64t a0 = 0, a1 = 0, a2 = 0, a3 = 0;
            const float* wv0 = &sm[WV_OFF + u*4];
            #pragma unroll 2
            for (int c = 0; c < CT; c += 4) {
                float4 ma4 = *reinterpret_cast<const float4*>(mA + c);
                float4 mb4 = *reinterpret_cast<const float4*>(mB + c);
                #pragma unroll
                for (int k = 0; k < 4; k++) {
                    float av = (&ma4.x)[k], bv = (&mb4.x)[k];
                    u64t aa = pk2(av, av), bb = pk2(bv, bv);
                    const float* wr = wv0 + (c + k) * 64;
                    ulonglong2 wA = *reinterpret_cast<const ulonglong2*>(wr);
                    ulonglong2 wB = *reinterpret_cast<const ulonglong2*>(wr + 32);
                    fma2(a0, aa, wA.x); fma2(a1, aa, wA.y);
                    fma2(a2, bb, wB.x); fma2(a3, bb, wB.y);
                }
            }
            float* oo = &sm[Q_OFF + p8*68 + u*4];
            *reinterpret_cast<ulonglong2*>(oo)      = make_ulonglong2(a0, a1);
            *reinterpret_cast<ulonglong2*>(oo + 32) = make_ulonglong2(a2, a3);
        }
        __syncwarp();

        // phase 5: out = O @ Wo + bo
        {
            u64t acc[8] = {0,0,0,0,0,0,0,0};
            const float* orow = &sm[Q_OFF + p8*68];
            const float* wo0  = &sm[WO_OFF + u*4];
            #pragma unroll 2
            for (int c = 0; c < 64; c += 4) {
                float4 ov = *reinterpret_cast<const float4*>(orow + c);
                #pragma unroll
                for (int k = 0; k < 4; k++) {
                    float o = (&ov.x)[k];
                    u64t oo2 = pk2(o, o);
                    const float* wr = wo0 + (c + k) * 128;
                    #pragma unroll
                    for (int b = 0; b < 4; b++) {
                        ulonglong2 w = *reinterpret_cast<const ulonglong2*>(wr + 32*b);
                        fma2(acc[2*b],   oo2, w.x);
                        fma2(acc[2*b+1], oo2, w.y);
                    }
                }
            }
            float* og = out + ((size_t)n0 + p8) * CZ + u*4;
            const float* bop = &sm[BO_OFF + u*4];
            #pragma unroll
            for (int b = 0; b < 4; b++) {
                ulonglong2 bo2 = *reinterpret_cast<const ulonglong2*>(bop + 32*b);
                add2(acc[2*b],   bo2.x);
                add2(acc[2*b+1], bo2.y);
                *reinterpret_cast<ulonglong2*>(og + 32*b) =
                    make_ulonglong2(acc[2*b], acc[2*b+1]);
            }
        }
        // next phase-0 write to Z is ordered by its own trailing __syncthreads,
        // and Z was last read before the phase-1 barrier of this iteration.
    }
}

extern "C" void kernel_launch(void* const* d_in, const int* in_sizes, int n_in,
                              void* d_out, int out_size)
{
    const float* t    = (const float*)d_in[0];
    const float* z    = (const float*)d_in[1];
    const float* mask = (const float*)d_in[2];
    const float* Wq   = (const float*)d_in[3];
    const float* Wk   = (const float*)d_in[4];
    const float* Wv   = (const float*)d_in[5];
    const float* Wo   = (const float*)d_in[6];
    const float* bo   = (const float*)d_in[7];
    float* out        = (float*)d_out;

    int nsm = 148;
    cudaDeviceGetAttribute(&nsm, cudaDevAttrMultiProcessorCount, 0);

    const size_t smem = (size_t)SMEM_FLOATS * sizeof(float);
    cudaFuncSetAttribute(tpa_kernel, cudaFuncAttributeMaxDynamicSharedMemorySize,
                         (int)smem);

    const int ntiles = NPIX / TILE;                 // 4096
    int grid = nsm < ntiles ? nsm : ntiles;
    tpa_kernel<<<grid, THREADS, smem>>>(t, z, mask, Wq, Wk, Wv, Wo, bo, out, ntiles);
}

// round 3
// speedup vs baseline: 1.0584x; 1.0584x over previous
#include <cuda_runtime.h>

#define RR      512
#define NPIX    (RR*RR)
#define CZ      128
#define CT      64
#define NH      4
#define NT      4
#define TILE    64
#define THREADS 512

// smem layout (float offsets)
#define WQ_OFF   0                      // [128][64]
#define WK_OFF   8192                   // [64] rows, stride 68
#define WV_OFF   (WK_OFF + 64*68)       // [64][64]
#define WO_OFF   (WV_OFF + 4096)        // [64][128]
#define BO_OFF   (WO_OFF + 8192)        // [128]
#define BIAS_OFF (BO_OFF + 128)         // [4]
#define Z_OFF    (BIAS_OFF + 4)         // [64] rows, stride 132
#define Q_OFF    (Z_OFF + 64*132)       // [64] rows, stride 68 (aliased by O)
#define QP_OFF   (Q_OFF + 64*68)        // [64] rows, stride 260 (Qp, then m)
#define SMEM_FLOATS (QP_OFF + 64*260)   // 54404 floats = 217616 B

typedef unsigned long long u64t;

__device__ __forceinline__ u64t pk2(float lo, float hi) {
    u64t r; asm("mov.b64 %0, {%1,%2};" : "=l"(r) : "f"(lo), "f"(hi)); return r;
}
__device__ __forceinline__ void upk2(u64t v, float &a, float &b) {
    asm("mov.b64 {%0,%1}, %2;" : "=f"(a), "=f"(b) : "l"(v));
}
__device__ __forceinline__ void fma2(u64t &acc, u64t a, u64t b) {
    asm("fma.rn.f32x2 %0, %1, %2, %0;" : "+l"(acc) : "l"(a), "l"(b));
}
__device__ __forceinline__ void add2(u64t &acc, u64t b) {
    asm("add.rn.f32x2 %0, %0, %1;" : "+l"(acc) : "l"(b));
}

__global__ void __launch_bounds__(THREADS, 1)
tpa_kernel(const float* __restrict__ t, const float* __restrict__ z,
           const float* __restrict__ mask,
           const float* __restrict__ Wq, const float* __restrict__ Wk,
           const float* __restrict__ Wv, const float* __restrict__ Wo,
           const float* __restrict__ bo, float* __restrict__ out, int ntiles)
{
    extern __shared__ float sm[];
    const int tid = threadIdx.x;

    // one-time weight staging
    for (int i = tid; i < 8192; i += THREADS) sm[WQ_OFF + i] = Wq[i] * 0.25f; // fold 16^-0.5
    for (int i = tid; i < 4096; i += THREADS) {
        int c = i >> 6, j = i & 63;
        sm[WK_OFF + c*68 + j] = Wk[i];
    }
    for (int i = tid; i < 4096; i += THREADS) sm[WV_OFF + i] = Wv[i];
    for (int i = tid; i < 8192; i += THREADS) sm[WO_OFF + i] = Wo[i];
    if (tid < 128) sm[BO_OFF + tid] = bo[tid];
    if (tid < 4)   sm[BIAS_OFF + tid] = 1e5f * (mask[tid] - 1.0f);
    __syncthreads();

    const int p8 = tid >> 3;   // pixel within tile
    const int u  = tid & 7;    // sub-slot

    for (int tile = blockIdx.x; tile < ntiles; tile += gridDim.x) {
        const int n0 = tile * TILE;

        // phase 0: stage Z tile [64][128] (row stride 132)
        {
            const float4* zg = reinterpret_cast<const float4*>(z + (size_t)n0 * CZ);
            #pragma unroll
            for (int r_ = 0; r_ < 4; r_++) {
                int e = tid + r_ * THREADS;          // 0..2047
                float4 v = zg[e];
                *reinterpret_cast<float4*>(&sm[Z_OFF + (e >> 5)*132 + (e & 31)*4]) = v;
            }
        }
        __syncthreads();

        // phase 1: Q = Z @ Wq'   (thread -> pixel p8, cols u*4..+3 and 32+u*4..+3)
        {
            u64t a0 = 0, a1 = 0, a2 = 0, a3 = 0;
            const float* zr  = &sm[Z_OFF + p8*132];
            const float* wq0 = &sm[WQ_OFF + u*4];
            #pragma unroll 2
            for (int c = 0; c < CZ; c += 4) {
                float4 zv = *reinterpret_cast<const float4*>(zr + c);
                #pragma unroll
                for (int k = 0; k < 4; k++) {
                    float zc = (&zv.x)[k];
                    u64t zz = pk2(zc, zc);
                    const float* wr = wq0 + (c + k) * 64;
                    ulonglong2 wa = *reinterpret_cast<const ulonglong2*>(wr);
                    ulonglong2 wb = *reinterpret_cast<const ulonglong2*>(wr + 32);
                    fma2(a0, zz, wa.x); fma2(a1, zz, wa.y);
                    fma2(a2, zz, wb.x); fma2(a3, zz, wb.y);
                }
            }
            float* qo = &sm[Q_OFF + p8*68 + u*4];
            *reinterpret_cast<ulonglong2*>(qo)      = make_ulonglong2(a0, a1);
            *reinterpret_cast<ulonglong2*>(qo + 32) = make_ulonglong2(a2, a3);
        }
        __syncthreads();

        // phase 2: Qp[p][h*64+c] = Q[p][h*16..] . Wk[c][h*16..]
        {
            const int h2  = tid >> 7;
            const int p2  = (tid >> 1) & 63;
            const int par = tid & 1;
            const float* qr = &sm[Q_OFF + p2*68 + h2*16];
            ulonglong2 qA = *reinterpret_cast<const ulonglong2*>(qr);
            ulonglong2 qB = *reinterpret_cast<const ulonglong2*>(qr + 4);
            ulonglong2 qC = *reinterpret_cast<const ulonglong2*>(qr + 8);
            ulonglong2 qD = *reinterpret_cast<const ulonglong2*>(qr + 12);
            float* qpo = &sm[QP_OFF + p2*260 + h2*64];
            const float* wb0 = &sm[WK_OFF + h2*16];
            #pragma unroll 4
            for (int i = 0; i < 32; i++) {
                const int c = 2*i + par;
                const float* wr = wb0 + c*68;
                u64t s0 = 0, s1 = 0;
                ulonglong2 w0 = *reinterpret_cast<const ulonglong2*>(wr);
                ulonglong2 w1 = *reinterpret_cast<const ulonglong2*>(wr + 4);
                ulonglong2 w2 = *reinterpret_cast<const ulonglong2*>(wr + 8);
                ulonglong2 w3 = *reinterpret_cast<const ulonglong2*>(wr + 12);
                fma2(s0, qA.x, w0.x); fma2(s1, qA.y, w0.y);
                fma2(s0, qB.x, w1.x); fma2(s1, qB.y, w1.y);
                fma2(s0, qC.x, w2.x); fma2(s1, qC.y, w2.y);
                fma2(s0, qD.x, w3.x); fma2(s1, qD.y, w3.y);
                float x0, x1, y0, y1; upk2(s0, x0, x1); upk2(s1, y0, y1);
                qpo[c] = (x0 + x1) + (y0 + y1);
            }
        }
        __syncthreads();

        // phase 3: logits + softmax + m   (8 threads per pixel, c-slice u*8..+7)
        {
            const int c0 = u * 8;
            const size_t nglob = (size_t)n0 + p8;
            ulonglong2 tv[NT][2];
            #pragma unroll
            for (int tt = 0; tt < NT; tt++) {
                const float* tp = t + ((size_t)tt * NPIX + nglob) * CT + c0;
                tv[tt][0] = *reinterpret_cast<const ulonglong2*>(tp);
                tv[tt][1] = *reinterpret_cast<const ulonglong2*>(tp + 4);
            }
            float lg[NH][NT];
            const float* qpr = &sm[QP_OFF + p8*260 + c0];
            #pragma unroll
            for (int h = 0; h < NH; h++) {
                ulonglong2 qa = *reinterpret_cast<const ulonglong2*>(qpr + h*64);
                ulonglong2 qb = *reinterpret_cast<const ulonglong2*>(qpr + h*64 + 4);
                #pragma unroll
                for (int tt = 0; tt < NT; tt++) {
                    u64t s = 0;
                    fma2(s, qa.x, tv[tt][0].x);
                    fma2(s, qa.y, tv[tt][0].y);
                    fma2(s, qb.x, tv[tt][1].x);
                    fma2(s, qb.y, tv[tt][1].y);
                    float x0, x1; upk2(s, x0, x1);
                    lg[h][tt] = x0 + x1;
                }
            }
            #pragma unroll
            for (int off = 4; off >= 1; off >>= 1)
                #pragma unroll
                for (int h = 0; h < NH; h++)
                    #pragma unroll
                    for (int tt = 0; tt < NT; tt++)
                        lg[h][tt] += __shfl_xor_sync(0xffffffffu, lg[h][tt], off, 8);

            const float b0 = sm[BIAS_OFF+0], b1 = sm[BIAS_OFF+1];
            const float b2 = sm[BIAS_OFF+2], b3 = sm[BIAS_OFF+3];
            float aw[NH][NT];
            #pragma unroll
            for (int h = 0; h < NH; h++) {
                float l0 = lg[h][0]+b0, l1 = lg[h][1]+b1;
                float l2 = lg[h][2]+b2, l3 = lg[h][3]+b3;
                float mx = fmaxf(fmaxf(l0,l1), fmaxf(l2,l3));
                float e0 = __expf(l0-mx), e1 = __expf(l1-mx);
                float e2 = __expf(l2-mx), e3 = __expf(l3-mx);
                float inv = 1.0f / (e0+e1+e2+e3);
                aw[h][0]=e0*inv; aw[h][1]=e1*inv; aw[h][2]=e2*inv; aw[h][3]=e3*inv;
            }
            __syncwarp();
            float* mp = &sm[QP_OFF + p8*260 + c0];
            #pragma unroll
            for (int h = 0; h < NH; h++) {
                u64t m0 = 0, m1 = 0, m2 = 0, m3 = 0;
                #pragma unroll
                for (int tt = 0; tt < NT; tt++) {
                    u64t av = pk2(aw[h][tt], aw[h][tt]);
                    fma2(m0, av, tv[tt][0].x);
                    fma2(m1, av, tv[tt][0].y);
                    fma2(m2, av, tv[tt][1].x);
                    fma2(m3, av, tv[tt][1].y);
                }
                *reinterpret_cast<ulonglong2*>(mp + h*64)     = make_ulonglong2(m0, m1);
                *reinterpret_cast<ulonglong2*>(mp + h*64 + 4) = make_ulonglong2(m2, m3);
            }
        }
        __syncwarp();

        // phase 4: O[p][hd] = sum_c m[p][hd>>4][c] * Wv[c][hd]  (O aliases Q)
        {
            const float* mA = &sm[QP_OFF + p8*260 + (u >> 2) * 64];  // head u>>2
            const float* mB = mA + 128;                               // head 2+(u>>2)
            u64t a0 = 0, a1 = 0, a2 = 0, a3 = 0;
            const float* wv0 = &sm[WV_OFF + u*4];
            #pragma unroll 2
            for (int c = 0; c < CT; c += 4) {
                float4 ma4 = *reinterpret_cast<const float4*>(mA + c);
                float4 mb4 = *reinterpret_cast<const float4*>(mB + c);
                #pragma unroll
                for (int k = 0; k < 4; k++) {
                    float av = (&ma4.x)[k], bv = (&mb4.x)[k];
                    u64t aa = pk2(av, av), bb = pk2(bv, bv);
                    const float* wr = wv0 + (c + k) * 64;
                    ulonglong2 wA = *reinterpret_cast<const ulonglong2*>(wr);
                    ulonglong2 wB = *reinterpret_cast<const ulonglong2*>(wr + 32);
                    fma2(a0, aa, wA.x); fma2(a1, aa, wA.y);
                    fma2(a2, bb, wB.x); fma2(a3, bb, wB.y);
                }
            }
            float* oo = &sm[Q_OFF + p8*68 + u*4];
            *reinterpret_cast<ulonglong2*>(oo)      = make_ulonglong2(a0, a1);
            *reinterpret_cast<ulonglong2*>(oo + 32) = make_ulonglong2(a2, a3);
        }
        __syncwarp();

        // phase 5: out = O @ Wo + bo
        {
            u64t acc[8] = {0,0,0,0,0,0,0,0};
            const float* orow = &sm[Q_OFF + p8*68];
            const float* wo0  = &sm[WO_OFF + u*4];
            #pragma unroll 2
            for (int c = 0; c < 64; c += 4) {
                float4 ov = *reinterpret_cast<const float4*>(orow + c);
                #pragma unroll
                for (int k = 0; k < 4; k++) {
                    float o = (&ov.x)[k];
                    u64t oo2 = pk2(o, o);
                    const float* wr = wo0 + (c + k) * 128;
                    #pragma unroll
                    for (int b = 0; b < 4; b++) {
                        ulonglong2 w = *reinterpret_cast<const ulonglong2*>(wr + 32*b);
                        fma2(acc[2*b],   oo2, w.x);
                        fma2(acc[2*b+1], oo2, w.y);
                    }
                }
            }
            float* og = out + ((size_t)n0 + p8) * CZ + u*4;
            const float* bop = &sm[BO_OFF + u*4];
            #pragma unroll
            for (int b = 0; b < 4; b++) {
                ulonglong2 bo2 = *reinterpret_cast<const ulonglong2*>(bop + 32*b);
                add2(acc[2*b],   bo2.x);
                add2(acc[2*b+1], bo2.y);
                *reinterpret_cast<ulonglong2*>(og + 32*b) =
                    make_ulonglong2(acc[2*b], acc[2*b+1]);
            }
        }
        // next phase-0 write to Z is ordered by its own trailing __syncthreads,
        // and Z was last read before the phase-1 barrier of this iteration.
    }
}

extern "C" void kernel_launch(void* const* d_in, const int* in_sizes, int n_in,
                              void* d_out, int out_size)
{
    const float* t    = (const float*)d_in[0];
    const float* z    = (const float*)d_in[1];
    const float* mask = (const float*)d_in[2];
    const float* Wq   = (const float*)d_in[3];
    const float* Wk   = (const float*)d_in[4];
    const float* Wv   = (const float*)d_in[5];
    const float* Wo   = (const float*)d_in[6];
    const float* bo   = (const float*)d_in[7];
    float* out        = (float*)d_out;

    int nsm = 148;
    cudaDeviceGetAttribute(&nsm, cudaDevAttrMultiProcessorCount, 0);

    const size_t smem = (size_t)SMEM_FLOATS * sizeof(float);
    cudaFuncSetAttribute(tpa_kernel, cudaFuncAttributeMaxDynamicSharedMemorySize,
                         (int)smem);

    const int ntiles = NPIX / TILE;                 // 4096
    int grid = nsm < ntiles ? nsm : ntiles;
    tpa_kernel<<<grid, THREADS, smem>>>(t, z, mask, Wq, Wk, Wv, Wo, bo, out, ntiles);
}

// round 4
// speedup vs baseline: 1.5961x; 1.5080x over previous
#include <cuda_runtime.h>

#define NPIX    (512*512)
#define TILE    128
#define THREADS 512
#define NTILES  (NPIX/TILE)

#define WQ   0
#define WKT  8192
#define WV   12288
#define WO   16384
#define BO   24576
#define BI   24704
#define ZQ   24708                 // [128][132] z, then Qp/m per pair
#define QB   (ZQ + 128*132)        // [128][68]
#define OP   (QB + 128*68)         // [128][36]
#define SMF  (OP + 128*36)         // 54916 floats

typedef unsigned long long u64t;

__device__ __forceinline__ u64t pk2(float v){u64t r;asm("mov.b64 %0,{%1,%1};":"=l"(r):"f"(v));return r;}
__device__ __forceinline__ void upk2(u64t v,float&a,float&b){asm("mov.b64 {%0,%1},%2;":"=f"(a),"=f"(b):"l"(v));}
__device__ __forceinline__ void fma2(u64t&acc,u64t a,u64t b){asm("fma.rn.f32x2 %0,%1,%2,%0;":"+l"(acc):"l"(a),"l"(b));}
__device__ __forceinline__ void add2(u64t&acc,u64t b){asm("add.rn.f32x2 %0,%0,%1;":"+l"(acc):"l"(b));}

// 4-pixel x NC-u64col microkernel: acc[j][c] += z[px_j][k] * w[k][c]
template<int NC,int K>
__device__ __forceinline__ void gb(const float* zb,int zstr,const float* wb,int wstr,u64t (&acc)[4][NC]){
    #pragma unroll 4
    for(int k=0;k<K;k+=4){
        float4 zv[4];
        #pragma unroll
        for(int j=0;j<4;j++) zv[j]=*(const float4*)(zb+j*zstr+k);
        #pragma unroll
        for(int kk=0;kk<4;kk++){
            const float* wr=wb+(k+kk)*wstr;
            u64t wv[NC];
            #pragma unroll
            for(int c2=0;c2<NC/2;c2++){
                float4 w4=*(const float4*)(wr+4*c2);
                wv[2*c2]  =reinterpret_cast<const u64t*>(&w4)[0];
                wv[2*c2+1]=reinterpret_cast<const u64t*>(&w4)[1];
            }
            #pragma unroll
            for(int j=0;j<4;j++){
                u64t zz=pk2((&zv[j].x)[kk]);
                #pragma unroll
                for(int c=0;c<NC;c++) fma2(acc[j][c],zz,wv[c]);
            }
        }
    }
}

__global__ void __launch_bounds__(THREADS,1)
tpa_kernel(const float* __restrict__ t,const float* __restrict__ z,
           const float* __restrict__ mask,
           const float* __restrict__ Wq,const float* __restrict__ Wk,
           const float* __restrict__ Wv_,const float* __restrict__ Wo,
           const float* __restrict__ bo,float* __restrict__ out,int ntiles)
{
    extern __shared__ float sm[];
    const int tid=threadIdx.x;

    for(int i=tid;i<8192;i+=THREADS) sm[WQ+i]=Wq[i]*0.25f;
    for(int i=tid;i<4096;i+=THREADS) sm[WKT+i]=Wk[(i&63)*64+(i>>6)];
    for(int i=tid;i<4096;i+=THREADS) sm[WV+i]=Wv_[i];
    for(int i=tid;i<8192;i+=THREADS) sm[WO+i]=Wo[i];
    if(tid<128) sm[BO+tid]=bo[tid];
    if(tid<4)   sm[BI+tid]=1e5f*(mask[tid]-1.0f);
    __syncthreads();

    const int pxg=tid>>4, cg=tid&15;        // P1,P2,P5
    const int p8=tid>>3,  u=tid&7;          // P3
    const int pg4=tid>>3, hh4=(tid&7)>>2, cgl=tid&3;  // P4 (tid<256)

    for(int tile=blockIdx.x;tile<ntiles;tile+=gridDim.x){
        const int n0=tile*TILE;

        // P0: stage z [128][128] -> ZQ (stride 132)
        {
            const float4* zg=(const float4*)(z+(size_t)n0*128);
            #pragma unroll
            for(int i=0;i<8;i++){
                int e=tid+i*THREADS;
                *(float4*)(&sm[ZQ+(e>>5)*132+(e&31)*4])=zg[e];
            }
        }
        __syncthreads();

        // P1: Q[128][64] = z @ Wq'
        {
            u64t acc[4][2]={};
            gb<2,128>(&sm[ZQ+pxg*4*132],132,&sm[WQ+cg*4],64,acc);
            #pragma unroll
            for(int j=0;j<4;j++)
                *(ulonglong2*)(&sm[QB+(pxg*4+j)*68+cg*4])=make_ulonglong2(acc[j][0],acc[j][1]);
        }
        __syncthreads();

        #pragma unroll
        for(int pr=0;pr<2;pr++){
            // P2: Qp (into ZQ): Qp[px][hh*68+c] = Q[px][h*16+.] @ Wkt
            #pragma unroll
            for(int hh=0;hh<2;hh++){
                const int h=pr*2+hh;
                u64t acc[4][2]={};
                gb<2,16>(&sm[QB+pxg*4*68+h*16],68,&sm[WKT+h*16*64+cg*4],64,acc);
                #pragma unroll
                for(int j=0;j<4;j++)
                    *(ulonglong2*)(&sm[ZQ+(pxg*4+j)*132+hh*68+cg*4])=make_ulonglong2(acc[j][0],acc[j][1]);
            }
            __syncthreads();

            // P3: logits + softmax + m (in place), 8 thr/px, 2 px halves
            #pragma unroll
            for(int it=0;it<2;it++){
                const int px=it*64+p8, c0=u*8;
                const size_t ng=(size_t)n0+px;
                ulonglong2 tv[4][2];
                #pragma unroll
                for(int tt=0;tt<4;tt++){
                    const float* tp=t+((size_t)tt*NPIX+ng)*64+c0;
                    tv[tt][0]=*(const ulonglong2*)tp;
                    tv[tt][1]=*(const ulonglong2*)(tp+4);
                }
                float* qrow=&sm[ZQ+px*132];
                float lg[2][4];
                #pragma unroll
                for(int hh=0;hh<2;hh++){
                    ulonglong2 qa=*(const ulonglong2*)(qrow+hh*68+c0);
                    ulonglong2 qb=*(const ulonglong2*)(qrow+hh*68+c0+4);
                    #pragma unroll
                    for(int tt=0;tt<4;tt++){
                        u64t s=0;
                        fma2(s,qa.x,tv[tt][0].x); fma2(s,qa.y,tv[tt][0].y);
                        fma2(s,qb.x,tv[tt][1].x); fma2(s,qb.y,tv[tt][1].y);
                        float x0,x1; upk2(s,x0,x1); lg[hh][tt]=x0+x1;
                    }
                }
                #pragma unroll
                for(int off=4;off>=1;off>>=1)
                    #pragma unroll
                    for(int hh=0;hh<2;hh++)
                        #pragma unroll
                        for(int tt=0;tt<4;tt++)
                            lg[hh][tt]+=__shfl_xor_sync(0xffffffffu,lg[hh][tt],off,8);
                const float b0=sm[BI+0],b1=sm[BI+1],b2=sm[BI+2],b3=sm[BI+3];
                #pragma unroll
                for(int hh=0;hh<2;hh++){
                    float l0=lg[hh][0]+b0,l1=lg[hh][1]+b1,l2=lg[hh][2]+b2,l3=lg[hh][3]+b3;
                    float mx=fmaxf(fmaxf(l0,l1),fmaxf(l2,l3));
                    float e0=__expf(l0-mx),e1=__expf(l1-mx),e2=__expf(l2-mx),e3=__expf(l3-mx);
                    float inv=1.0f/(e0+e1+e2+e3);
                    u64t a0=pk2(e0*inv),a1=pk2(e1*inv),a2=pk2(e2*inv),a3=pk2(e3*inv);
                    u64t m0=0,m1=0,m2=0,m3=0;
                    fma2(m0,a0,tv[0][0].x); fma2(m1,a0,tv[0][0].y); fma2(m2,a0,tv[0][1].x); fma2(m3,a0,tv[0][1].y);
                    fma2(m0,a1,tv[1][0].x); fma2(m1,a1,tv[1][0].y); fma2(m2,a1,tv[1][1].x); fma2(m3,a1,tv[1][1].y);
                    fma2(m0,a2,tv[2][0].x); fma2(m1,a2,tv[2][0].y); fma2(m2,a2,tv[2][1].x); fma2(m3,a2,tv[2][1].y);
                    fma2(m0,a3,tv[3][0].x); fma2(m1,a3,tv[3][0].y); fma2(m2,a3,tv[3][1].x); fma2(m3,a3,tv[3][1].y);
                    *(ulonglong2*)(qrow+hh*68+c0)  =make_ulonglong2(m0,m1);
                    *(ulonglong2*)(qrow+hh*68+c0+4)=make_ulonglong2(m2,m3);
                }
            }
            __syncthreads();

            // P4: OP[px][hh*16+d] = m_h @ Wv_h (K=64); threads 0..255
            if(tid<256){
                const int h=pr*2+hh4;
                u64t acc[4][2]={};
                gb<2,64>(&sm[ZQ+pg4*4*132+hh4*68],132,&sm[WV+h*16+cgl*4],64,acc);
                #pragma unroll
                for(int j=0;j<4;j++)
                    *(ulonglong2*)(&sm[OP+(pg4*4+j)*36+hh4*16+cgl*4])=make_ulonglong2(acc[j][0],acc[j][1]);
            }
            __syncthreads();

            // P5: out[px][cg*8..+7] += OP @ Wo[pr*32..] (K=32); pair0 init with bo
            {
                u64t acc[4][4]={};
                gb<4,32>(&sm[OP+pxg*4*36],36,&sm[WO+pr*32*128+cg*8],128,acc);
                #pragma unroll
                for(int j=0;j<4;j++){
                    float* og=out+((size_t)n0+pxg*4+j)*128+cg*8;
                    u64t p0,p1,p2,p3;
                    if(pr==0){
                        float4 w0=*(const float4*)(&sm[BO+cg*8]);
                        float4 w1=*(const float4*)(&sm[BO+cg*8+4]);
                        p0=reinterpret_cast<const u64t*>(&w0)[0]; p1=reinterpret_cast<const u64t*>(&w0)[1];
                        p2=reinterpret_cast<const u64t*>(&w1)[0]; p3=reinterpret_cast<const u64t*>(&w1)[1];
                    }else{
                        ulonglong2 o0=*(const ulonglong2*)og, o1=*(const ulonglong2*)(og+4);
                        p0=o0.x; p1=o0.y; p2=o1.x; p3=o1.y;
                    }
                    add2(acc[j][0],p0); add2(acc[j][1],p1); add2(acc[j][2],p2); add2(acc[j][3],p3);
                    *(ulonglong2*)og    =make_ulonglong2(acc[j][0],acc[j][1]);
                    *(ulonglong2*)(og+4)=make_ulonglong2(acc[j][2],acc[j][3]);
                }
            }
        }
    }
}

extern "C" void kernel_launch(void* const* d_in,const int* in_sizes,int n_in,
                              void* d_out,int out_size)
{
    const float* t  =(const float*)d_in[0];
    const float* z  =(const float*)d_in[1];
    const float* mk =(const float*)d_in[2];
    const float* wq =(const float*)d_in[3];
    const float* wk =(const float*)d_in[4];
    const float* wv =(const float*)d_in[5];
    const float* wo =(const float*)d_in[6];
    const float* bo =(const float*)d_in[7];
    float* out=(float*)d_out;

    int nsm=148;
    cudaDeviceGetAttribute(&nsm,cudaDevAttrMultiProcessorCount,0);
    const size_t smem=(size_t)SMF*sizeof(float);
    cudaFuncSetAttribute(tpa_kernel,cudaFuncAttributeMaxDynamicSharedMemorySize,(int)smem);
    int grid=nsm<NTILES?nsm:NTILES;
    tpa_kernel<<<grid,THREADS,smem>>>(t,z,mk,wq,wk,wv,wo,bo,out,NTILES);
}

// round 5
// speedup vs baseline: 1.7068x; 1.0693x over previous
#include <cuda_runtime.h>

#define NPIX    (512*512)
#define TILE    128
#define THREADS 512
#define NTILES  (NPIX/TILE)

#define WQ   0
#define WKT  8192
#define WV   12288
#define WO   16384
#define BO   24576
#define BI   24704
#define ZQ   24708                 // [128][132] z, then Qp/m per pair
#define QB   (ZQ + 128*132)        // [128][68]
#define OP   (QB + 128*68)         // [128][36]
#define SMF  (OP + 128*36)

typedef unsigned long long u64t;

__device__ __forceinline__ u64t pk2(float v){u64t r;asm("mov.b64 %0,{%1,%1};":"=l"(r):"f"(v));return r;}
__device__ __forceinline__ void upk2(u64t v,float&a,float&b){asm("mov.b64 {%0,%1},%2;":"=f"(a),"=f"(b):"l"(v));}
__device__ __forceinline__ void fma2(u64t&acc,u64t a,u64t b){asm("fma.rn.f32x2 %0,%1,%2,%0;":"+l"(acc):"l"(a),"l"(b));}
__device__ __forceinline__ void add2(u64t&acc,u64t b){asm("add.rn.f32x2 %0,%0,%1;":"+l"(acc):"l"(b));}

// 4-row x NC-u64col microkernel; rows j are jstr apart
template<int NC,int K>
__device__ __forceinline__ void gb(const float* zb,int jstr,const float* wb,int wstr,u64t (&acc)[4][NC]){
    #pragma unroll 4
    for(int k=0;k<K;k+=4){
        float4 zv[4];
        #pragma unroll
        for(int j=0;j<4;j++) zv[j]=*(const float4*)(zb+j*jstr+k);
        #pragma unroll
        for(int kk=0;kk<4;kk++){
            const float* wr=wb+(k+kk)*wstr;
            u64t wv[NC];
            #pragma unroll
            for(int c2=0;c2<NC/2;c2++){
                float4 w4=*(const float4*)(wr+4*c2);
                wv[2*c2]  =reinterpret_cast<const u64t*>(&w4)[0];
                wv[2*c2+1]=reinterpret_cast<const u64t*>(&w4)[1];
            }
            #pragma unroll
            for(int j=0;j<4;j++){
                u64t zz=pk2((&zv[j].x)[kk]);
                #pragma unroll
                for(int c=0;c<NC;c++) fma2(acc[j][c],zz,wv[c]);
            }
        }
    }
}

__global__ void __launch_bounds__(THREADS,1)
tpa_kernel(const float* __restrict__ t,const float* __restrict__ z,
           const float* __restrict__ mask,
           const float* __restrict__ Wq,const float* __restrict__ Wk,
           const float* __restrict__ Wv_,const float* __restrict__ Wo,
           const float* __restrict__ bo,float* __restrict__ out,int ntiles)
{
    extern __shared__ float sm[];
    const int tid=threadIdx.x;

    for(int i=tid;i<8192;i+=THREADS) sm[WQ+i]=Wq[i]*0.25f;
    for(int i=tid;i<4096;i+=THREADS) sm[WKT+i]=Wk[(i&63)*64+(i>>6)];
    for(int i=tid;i<4096;i+=THREADS) sm[WV+i]=Wv_[i];
    for(int i=tid;i<8192;i+=THREADS) sm[WO+i]=Wo[i];
    if(tid<128) sm[BO+tid]=bo[tid];
    if(tid<4)   sm[BI+tid]=1e5f*(mask[tid]-1.0f);
    __syncthreads();

    const int lane=tid&31, w=tid>>5;
    const int lpx=lane>>2, lcol=lane&3;
    // P1/P2: warp = 32px x 16col; thread px set {px1 + j*8}
    const int px1=(w&3)*32+lpx;
    const int c1 =(w>>2)*16+lcol*4;
    // P5: warp = 32px x 32col
    const int c5 =(w>>2)*32+lcol*8;
    // P4 (tid<256): px set {px4 + j*4}
    const int px4=(tid>>5)*16+((tid>>3)&3);
    const int hh4=(tid&7)>>2, cgl=tid&3;
    // P3
    const int p8=tid>>3, u=tid&7;

    for(int tile=blockIdx.x;tile<ntiles;tile+=gridDim.x){
        const int n0=tile*TILE;

        // P0: stage z [128][128] -> ZQ (stride 132)
        {
            const float4* zg=(const float4*)(z+(size_t)n0*128);
            #pragma unroll
            for(int i=0;i<8;i++){
                int e=tid+i*THREADS;
                *(float4*)(&sm[ZQ+(e>>5)*132+(e&31)*4])=zg[e];
            }
        }
        __syncthreads();

        // P1: Q[128][64] = z @ Wq'
        {
            u64t acc[4][2]={};
            gb<2,128>(&sm[ZQ+px1*132],8*132,&sm[WQ+c1],64,acc);
            #pragma unroll
            for(int j=0;j<4;j++)
                *(ulonglong2*)(&sm[QB+(px1+j*8)*68+c1])=make_ulonglong2(acc[j][0],acc[j][1]);
        }
        __syncthreads();

        #pragma unroll
        for(int pr=0;pr<2;pr++){
            // P2: Qp[px][hh*68+c] = Q[px][h*16+.] @ Wkt   (into ZQ)
            #pragma unroll
            for(int hh=0;hh<2;hh++){
                const int h=pr*2+hh;
                u64t acc[4][2]={};
                gb<2,16>(&sm[QB+px1*68+h*16],8*68,&sm[WKT+h*16*64+c1],64,acc);
                #pragma unroll
                for(int j=0;j<4;j++)
                    *(ulonglong2*)(&sm[ZQ+(px1+j*8)*132+hh*68+c1])=make_ulonglong2(acc[j][0],acc[j][1]);
            }
            __syncthreads();

            // P3: logits + softmax + m (in place), 8 thr/px, 2 px halves
            #pragma unroll
            for(int it=0;it<2;it++){
                const int px=it*64+p8, c0=u*8;
                const size_t ng=(size_t)n0+px;
                ulonglong2 tv[4][2];
                #pragma unroll
                for(int tt=0;tt<4;tt++){
                    const float* tp=t+((size_t)tt*NPIX+ng)*64+c0;
                    tv[tt][0]=*(const ulonglong2*)tp;
                    tv[tt][1]=*(const ulonglong2*)(tp+4);
                }
                float* qrow=&sm[ZQ+px*132];
                float lg[2][4];
                #pragma unroll
                for(int hh=0;hh<2;hh++){
                    ulonglong2 qa=*(const ulonglong2*)(qrow+hh*68+c0);
                    ulonglong2 qb=*(const ulonglong2*)(qrow+hh*68+c0+4);
                    #pragma unroll
                    for(int tt=0;tt<4;tt++){
                        u64t s=0;
                        fma2(s,qa.x,tv[tt][0].x); fma2(s,qa.y,tv[tt][0].y);
                        fma2(s,qb.x,tv[tt][1].x); fma2(s,qb.y,tv[tt][1].y);
                        float x0,x1; upk2(s,x0,x1); lg[hh][tt]=x0+x1;
                    }
                }
                #pragma unroll
                for(int off=4;off>=1;off>>=1)
                    #pragma unroll
                    for(int hh=0;hh<2;hh++)
                        #pragma unroll
                        for(int tt=0;tt<4;tt++)
                            lg[hh][tt]+=__shfl_xor_sync(0xffffffffu,lg[hh][tt],off,8);
                const float b0=sm[BI+0],b1=sm[BI+1],b2=sm[BI+2],b3=sm[BI+3];
                #pragma unroll
                for(int hh=0;hh<2;hh++){
                    float l0=lg[hh][0]+b0,l1=lg[hh][1]+b1,l2=lg[hh][2]+b2,l3=lg[hh][3]+b3;
                    float mx=fmaxf(fmaxf(l0,l1),fmaxf(l2,l3));
                    float e0=__expf(l0-mx),e1=__expf(l1-mx),e2=__expf(l2-mx),e3=__expf(l3-mx);
                    float inv=1.0f/(e0+e1+e2+e3);
                    u64t a0=pk2(e0*inv),a1=pk2(e1*inv),a2=pk2(e2*inv),a3=pk2(e3*inv);
                    u64t m0=0,m1=0,m2=0,m3=0;
                    fma2(m0,a0,tv[0][0].x); fma2(m1,a0,tv[0][0].y); fma2(m2,a0,tv[0][1].x); fma2(m3,a0,tv[0][1].y);
                    fma2(m0,a1,tv[1][0].x); fma2(m1,a1,tv[1][0].y); fma2(m2,a1,tv[1][1].x); fma2(m3,a1,tv[1][1].y);
                    fma2(m0,a2,tv[2][0].x); fma2(m1,a2,tv[2][0].y); fma2(m2,a2,tv[2][1].x); fma2(m3,a2,tv[2][1].y);
                    fma2(m0,a3,tv[3][0].x); fma2(m1,a3,tv[3][0].y); fma2(m2,a3,tv[3][1].x); fma2(m3,a3,tv[3][1].y);
                    *(ulonglong2*)(qrow+hh*68+c0)  =make_ulonglong2(m0,m1);
                    *(ulonglong2*)(qrow+hh*68+c0+4)=make_ulonglong2(m2,m3);
                }
            }
            __syncthreads();

            // P4: OP[px][hh*16+d] = m_h @ Wv_h (K=64); threads 0..255
            if(tid<256){
                const int h=pr*2+hh4;
                u64t acc[4][2]={};
                gb<2,64>(&sm[ZQ+px4*132+hh4*68],4*132,&sm[WV+h*16+cgl*4],64,acc);
                #pragma unroll
                for(int j=0;j<4;j++)
                    *(ulonglong2*)(&sm[OP+(px4+j*4)*36+hh4*16+cgl*4])=make_ulonglong2(acc[j][0],acc[j][1]);
            }
            __syncthreads();

            // P5: out[px][c5..+7] += OP @ Wo[pr*32..] (K=32); pair0 init with bo
            {
                u64t acc[4][4]={};
                gb<4,32>(&sm[OP+px1*36],8*36,&sm[WO+pr*32*128+c5],128,acc);
                #pragma unroll
                for(int j=0;j<4;j++){
                    float* og=out+((size_t)n0+px1+j*8)*128+c5;
                    u64t p0,p1,p2,p3;
                    if(pr==0){
                        float4 w0=*(const float4*)(&sm[BO+c5]);
                        float4 w1=*(const float4*)(&sm[BO+c5+4]);
                        p0=reinterpret_cast<const u64t*>(&w0)[0]; p1=reinterpret_cast<const u64t*>(&w0)[1];
                        p2=reinterpret_cast<const u64t*>(&w1)[0]; p3=reinterpret_cast<const u64t*>(&w1)[1];
                    }else{
                        ulonglong2 o0=*(const ulonglong2*)og, o1=*(const ulonglong2*)(og+4);
                        p0=o0.x; p1=o0.y; p2=o1.x; p3=o1.y;
                    }
                    add2(acc[j][0],p0); add2(acc[j][1],p1); add2(acc[j][2],p2); add2(acc[j][3],p3);
                    *(ulonglong2*)og    =make_ulonglong2(acc[j][0],acc[j][1]);
                    *(ulonglong2*)(og+4)=make_ulonglong2(acc[j][2],acc[j][3]);
                }
            }
        }
    }
}

extern "C" void kernel_launch(void* const* d_in,const int* in_sizes,int n_in,
                              void* d_out,int out_size)
{
    const float* t  =(const float*)d_in[0];
    const float* z  =(const float*)d_in[1];
    const float* mk =(const float*)d_in[2];
    const float* wq =(const float*)d_in[3];
    const float* wk =(const float*)d_in[4];
    const float* wv =(const float*)d_in[5];
    const float* wo =(const float*)d_in[6];
    const float* bo =(const float*)d_in[7];
    float* out=(float*)d_out;

    int nsm=148;
    cudaDeviceGetAttribute(&nsm,cudaDevAttrMultiProcessorCount,0);
    const size_t smem=(size_t)SMF*sizeof(float);
    cudaFuncSetAttribute(tpa_kernel,cudaFuncAttributeMaxDynamicSharedMemorySize,(int)smem);
    int grid=nsm<NTILES?nsm:NTILES;
    tpa_kernel<<<grid,THREADS,smem>>>(t,z,mk,wq,wk,wv,wo,bo,out,NTILES);
}